// round 10
// baseline (speedup 1.0000x reference)
#include <cuda_runtime.h>
#include <cuda_fp16.h>
#include <cstdint>

// Problem constants (fixed shapes)
#define BB 4
#define SS 1024
#define DD 1024
#define HH 16
#define DHH 64
#define RR (BB*SS)        // 4096 rows
#define NELEM (RR*DD)     // 4194304

// Scratch (device globals: no allocation allowed)
__device__ float d_g[NELEM];    // GEMM output (pre-BN)
__device__ float d_h0[NELEM];   // post-BN hidden state (fused attn input)
__device__ __half d_kh[6 * (size_t)NELEM];   // K fp16, layout [st][b][hd][s][64]
__device__ __half d_vh[6 * (size_t)NELEM];   // V fp16, layout [st][b][hd][s][64]
__device__ float g_sum[DD];
__device__ float g_sqsum[DD];
__device__ float g_nmul[DD];
__device__ float g_nadd[DD];

// ---------------------------------------------------------------------------
// helpers
// ---------------------------------------------------------------------------
__device__ __forceinline__ uint32_t f2h2(float a, float b) {
    __half2 h = __floats2half2_rn(a, b);
    return *(uint32_t*)&h;
}

__device__ __forceinline__ uint32_t hadd2u(uint32_t a, uint32_t b) {
    __half2 r = __hadd2(*(__half2*)&a, *(__half2*)&b);
    return *(uint32_t*)&r;
}

__device__ __forceinline__ float ex2f(float x) {
    float r; asm("ex2.approx.f32 %0, %1;" : "=f"(r) : "f"(x)); return r;
}

__device__ __forceinline__ void mma16(float* c,
                                      uint32_t a0, uint32_t a1, uint32_t a2, uint32_t a3,
                                      uint32_t b0, uint32_t b1) {
    asm volatile("mma.sync.aligned.m16n8k16.row.col.f32.f16.f16.f32 "
                 "{%0,%1,%2,%3},{%4,%5,%6,%7},{%8,%9},{%0,%1,%2,%3};"
                 : "+f"(c[0]), "+f"(c[1]), "+f"(c[2]), "+f"(c[3])
                 : "r"(a0), "r"(a1), "r"(a2), "r"(a3), "r"(b0), "r"(b1));
}

__device__ __forceinline__ void ldsm4t(uint32_t& r0, uint32_t& r1, uint32_t& r2, uint32_t& r3,
                                       uint32_t addr) {
    asm volatile("ldmatrix.sync.aligned.m8n8.x4.trans.shared.b16 {%0,%1,%2,%3}, [%4];"
                 : "=r"(r0), "=r"(r1), "=r"(r2), "=r"(r3) : "r"(addr));
}

__device__ __forceinline__ uint32_t smem_u32(const void* p) {
    uint32_t a;
    asm("{ .reg .u64 t; cvta.to.shared.u64 t, %1; cvt.u32.u64 %0, t; }" : "=r"(a) : "l"(p));
    return a;
}

__device__ __forceinline__ void cp16(uint32_t smem, const void* gmem) {
    asm volatile("cp.async.cg.shared.global [%0], [%1], 16;" :: "r"(smem), "l"(gmem));
}
__device__ __forceinline__ void cp_commit() { asm volatile("cp.async.commit_group;"); }
__device__ __forceinline__ void cp_wait0()  { asm volatile("cp.async.wait_group 0;" ::: "memory"); }

// ---------------------------------------------------------------------------
// Preconvert K/V to fp16, head-major: dst[st][b][hd][s][64].
// grid (SS/16, BB*HH, 12); block 256 (16 s-rows x 16 thr x float4).
// ---------------------------------------------------------------------------
__global__ __launch_bounds__(256) void conv_kernel(
    const float* k0, const float* k1, const float* k2,
    const float* k3, const float* k4, const float* k5,
    const float* v0, const float* v1, const float* v2,
    const float* v3, const float* v4, const float* v5) {
    const float* srcs[12] = {k0, k1, k2, k3, k4, k5, v0, v1, v2, v3, v4, v5};
    const int t = blockIdx.z;            // 0-5 K stages, 6-11 V stages
    const int st = (t < 6) ? t : t - 6;
    const float* src = srcs[t];
    __half* dstb = (t < 6) ? d_kh : d_vh;

    const int b = blockIdx.y >> 4, hd = blockIdx.y & 15;
    const int srow = blockIdx.x * 16 + (threadIdx.x >> 4);
    const int d4 = (threadIdx.x & 15) * 4;

    float4 v = *(const float4*)(src + (size_t)b * (SS * DD) + (size_t)srow * DD + hd * DHH + d4);
    __half* dst = dstb + ((((size_t)st * BB + b) * HH + hd) * SS + srow) * DHH + d4;
    uint32_t* d32 = (uint32_t*)dst;
    d32[0] = f2h2(v.x, v.y);
    d32[1] = f2h2(v.z, v.w);
}

// ---------------------------------------------------------------------------
// GEMM: d_g[r,o] = (sum_i x[r,i] * W[o,i]) * scale[o]   (fp16 MMA, fp32 acc)
// ---------------------------------------------------------------------------
#define LDW 36

__global__ __launch_bounds__(256) void gemm_kernel(const float* __restrict__ x,
                                                   const float* __restrict__ W,
                                                   const float* __restrict__ scale) {
    __shared__ __align__(16) uint32_t Xs[128 * LDW];
    __shared__ __align__(16) uint32_t Ws[64 * LDW];
    const int tid = threadIdx.x;
    const int lane = tid & 31, w = tid >> 5;
    const int wq = w * 16;
    const int r4 = lane >> 2, c4 = lane & 3;
    const int r0 = blockIdx.y * 128, o0 = blockIdx.x * 64;

    float acc[8][4];
#pragma unroll
    for (int n = 0; n < 8; n++)
#pragma unroll
        for (int j = 0; j < 4; j++) acc[n][j] = 0.f;

    for (int k0 = 0; k0 < DD; k0 += 64) {
#pragma unroll
        for (int it = 0; it < 8; it++) {
            int idx = tid + it * 256;
            int r = idx >> 4, d4 = (idx & 15) * 4;
            float4 v = *(const float4*)(x + (size_t)(r0 + r) * DD + k0 + d4);
            uint32_t* dst = Xs + r * LDW + (idx & 15) * 2;
            dst[0] = f2h2(v.x, v.y); dst[1] = f2h2(v.z, v.w);
        }
#pragma unroll
        for (int it = 0; it < 4; it++) {
            int idx = tid + it * 256;
            int r = idx >> 4, d4 = (idx & 15) * 4;
            float4 v = *(const float4*)(W + (size_t)(o0 + r) * DD + k0 + d4);
            uint32_t* dst = Ws + r * LDW + (idx & 15) * 2;
            dst[0] = f2h2(v.x, v.y); dst[1] = f2h2(v.z, v.w);
        }
        __syncthreads();

#pragma unroll
        for (int k16 = 0; k16 < 4; k16++) {
            const uint32_t* xp = Xs + (wq + r4) * LDW + k16 * 8 + c4;
            uint32_t a0 = xp[0], a1 = xp[8 * LDW], a2 = xp[4], a3 = xp[8 * LDW + 4];
#pragma unroll
            for (int n = 0; n < 8; n++) {
                const uint32_t* wp = Ws + (n * 8 + r4) * LDW + k16 * 8 + c4;
                mma16(acc[n], a0, a1, a2, a3, wp[0], wp[4]);
            }
        }
        __syncthreads();
    }

#pragma unroll
    for (int h = 0; h < 2; h++) {
        int row = r0 + wq + h * 8 + r4;
#pragma unroll
        for (int n = 0; n < 8; n++) {
            float2 sc = *(const float2*)(scale + o0 + n * 8 + c4 * 2);
            float2 ov = make_float2(acc[n][h * 2] * sc.x, acc[n][h * 2 + 1] * sc.y);
            *(float2*)(d_g + (size_t)row * DD + o0 + n * 8 + c4 * 2) = ov;
        }
    }
}

// ---------------------------------------------------------------------------
// BatchNorm statistics
// ---------------------------------------------------------------------------
__global__ __launch_bounds__(256) void zero_stats_kernel() {
    int i = blockIdx.x * 256 + threadIdx.x;
    if (i < DD) { g_sum[i] = 0.f; g_sqsum[i] = 0.f; }
}

__global__ __launch_bounds__(256) void stats_partial_kernel() {
    int r0 = blockIdx.x * 64;
    float s[4] = {0.f, 0.f, 0.f, 0.f};
    float ss[4] = {0.f, 0.f, 0.f, 0.f};
    for (int r = 0; r < 64; r++) {
        const float* row = d_g + (size_t)(r0 + r) * DD;
#pragma unroll
        for (int c = 0; c < 4; c++) {
            float v = row[threadIdx.x + c * 256];
            s[c] += v; ss[c] += v * v;
        }
    }
#pragma unroll
    for (int c = 0; c < 4; c++) {
        atomicAdd(&g_sum[threadIdx.x + c * 256], s[c]);
        atomicAdd(&g_sqsum[threadIdx.x + c * 256], ss[c]);
    }
}

__global__ __launch_bounds__(256) void finalize_kernel(const float* __restrict__ gamma,
                                                       const float* __restrict__ beta) {
    int f = blockIdx.x * 256 + threadIdx.x;
    if (f < DD) {
        float mu = g_sum[f] * (1.f / RR);
        float var = g_sqsum[f] * (1.f / RR) - mu * mu;
        float rs = rsqrtf(var + 1e-5f);
        float gm = gamma[f] * rs;
        g_nmul[f] = gm;
        g_nadd[f] = beta[f] - gm * mu;
    }
}

// ---------------------------------------------------------------------------
// Elementwise epilogue -> d_h0
// ---------------------------------------------------------------------------
__global__ __launch_bounds__(256) void post_kernel(const float* __restrict__ mask,
                                                   const float* __restrict__ resid,
                                                   const float* __restrict__ attn,
                                                   const float* __restrict__ pos) {
    int i = blockIdx.x * 256 + threadIdx.x;
    int fb = (i & 255) * 4;
    float4 gv = *(const float4*)(d_g + (size_t)i * 4);
    float4 mk = ((const float4*)mask)[i];
    float4 rv = ((const float4*)resid)[i];
    float4 av = ((const float4*)attn)[i];
    float4 pv = ((const float4*)pos)[i];
    float g[4] = {gv.x, gv.y, gv.z, gv.w};
    float m[4] = {mk.x, mk.y, mk.z, mk.w};
    float r[4] = {rv.x, rv.y, rv.z, rv.w};
    float a[4] = {av.x, av.y, av.z, av.w};
    float p[4] = {pv.x, pv.y, pv.z, pv.w};
    float o[4];
#pragma unroll
    for (int c = 0; c < 4; c++) {
        float h = g[c] * g_nmul[fb + c] + g_nadd[fb + c];
        h = fmaxf(h, 0.f) * m[c];
        o[c] = h + r[c] + a[c] + p[c];
    }
    *(float4*)(d_h0 + (size_t)i * 4) = make_float4(o[0], o[1], o[2], o[3]);
}

// ---------------------------------------------------------------------------
// Fused 6-stage flash attention. h lives in SMEM (Hs) across stages
// (row-local recurrence; avoids register spills under launch_bounds(256,2)).
//   per stage: h += MHA(h + qb, K_st, V_st)
// K/V preconverted fp16 head-major, cp.async double-buffered, KT=64.
// ---------------------------------------------------------------------------
#define QT 128
#define KT 64
#define LDH 36                       // uint32 (half2) row stride
#define VROWB (LDH * 4)              // smem tile row stride in bytes = 144
#define SCL 0.18033688f              // (1/sqrt(64)) * log2(e)

// smem word layout
#define SM_K0 0
#define SM_K1 2304
#define SM_V0 4608
#define SM_V1 6912
#define SM_P  9216
#define SM_H  13824                  // 128 x 68 fp32
#define SM_WORDS (SM_H + QT * 68)    // 22528 u32 = 90112 B

__global__ __launch_bounds__(256, 2) void fused_attn(
    const float* __restrict__ h0,
    const float* __restrict__ q0p, const float* __restrict__ q1p,
    const float* __restrict__ q2p, const float* __restrict__ q3p,
    const float* __restrict__ q4p, const float* __restrict__ q5p,
    const __half* __restrict__ khb, const __half* __restrict__ vhb,
    float* __restrict__ out) {
    extern __shared__ __align__(16) uint32_t sm[];
    uint32_t* Ps = sm + SM_P;
    float* Hs = (float*)(sm + SM_H);     // [128][68] fp32 hidden state

    const int tid = threadIdx.x;
    const int lane = tid & 31, w = tid >> 5;
    const int wq = w * 16;
    const int r4 = lane >> 2, c4 = lane & 3;

    const int bh = blockIdx.x;
    const int b = bh >> 4, hd = bh & 15;
    const int q0r = blockIdx.y * QT;
    const size_t base = (size_t)b * (SS * DD) + (size_t)hd * DHH;    // fp32 tensors
    const size_t hbase = (size_t)bh * (SS * DHH);                    // head-major fp16

    const float* qps[6] = {q0p, q1p, q2p, q3p, q4p, q5p};

    // cp.async chunk mapping: 2x16B chunks per tensor per tile per thread
    const int c0 = tid * 2;
    const int prow0 = c0 >> 3, poff0 = (c0 & 7) * 16;        // tile row / byte offset
    const int prow1 = (c0 + 1) >> 3, poff1 = ((c0 + 1) & 7) * 16;
    const uint32_t smbase = smem_u32(sm);
    const uint32_t kby[2] = {smbase + SM_K0 * 4, smbase + SM_K1 * 4};
    const uint32_t vby[2] = {smbase + SM_V0 * 4, smbase + SM_V1 * 4};
    const uint32_t vb32[2] = {vby[0] + (lane & 15) * VROWB + (lane >> 4) * 16,
                              vby[1] + (lane & 15) * VROWB + (lane >> 4) * 16};

    // ---- initial h -> Hs (coalesced) ----
#pragma unroll
    for (int it = 0; it < 8; it++) {
        int idx = tid + it * 256;
        int row = idx >> 4, d4 = (idx & 15) * 4;
        *(float4*)(Hs + row * 68 + d4) =
            *(const float4*)(h0 + base + (size_t)(q0r + row) * DD + d4);
    }
    __syncthreads();

#pragma unroll 1
    for (int st = 0; st < 6; st++) {
        // ---- stage qb -> Ps (half2), then build Q A-fragments from Hs + Ps ----
        const float* qb = qps[st];
#pragma unroll
        for (int it = 0; it < 8; it++) {
            int idx = tid + it * 256;
            int row = idx >> 4, d4 = (idx & 15) * 4;
            float4 v = *(const float4*)(qb + base + (size_t)(q0r + row) * DD + d4);
            uint32_t* dst = Ps + row * LDH + (idx & 15) * 2;
            dst[0] = f2h2(v.x, v.y); dst[1] = f2h2(v.z, v.w);
        }
        __syncthreads();
        uint32_t qA[4][4];
#pragma unroll
        for (int g = 0; g < 4; g++) {
            const uint32_t* pr0 = Ps + (wq + r4) * LDH + g * 8 + c4;
            const uint32_t* pr1 = Ps + (wq + 8 + r4) * LDH + g * 8 + c4;
            float2 h00 = *(float2*)(Hs + (wq + r4) * 68 + g * 16 + c4 * 2);
            float2 h01 = *(float2*)(Hs + (wq + 8 + r4) * 68 + g * 16 + c4 * 2);
            float2 h10 = *(float2*)(Hs + (wq + r4) * 68 + g * 16 + 8 + c4 * 2);
            float2 h11 = *(float2*)(Hs + (wq + 8 + r4) * 68 + g * 16 + 8 + c4 * 2);
            qA[g][0] = hadd2u(f2h2(h00.x, h00.y), pr0[0]);
            qA[g][1] = hadd2u(f2h2(h01.x, h01.y), pr1[0]);
            qA[g][2] = hadd2u(f2h2(h10.x, h10.y), pr0[4]);
            qA[g][3] = hadd2u(f2h2(h11.x, h11.y), pr1[4]);
        }

        const __half* kh = khb + (size_t)st * NELEM + hbase;
        const __half* vh = vhb + (size_t)st * NELEM + hbase;

        float o[8][4];
#pragma unroll
        for (int n = 0; n < 8; n++)
#pragma unroll
            for (int j = 0; j < 4; j++) o[n][j] = 0.f;
        float mx[2] = {-1e30f, -1e30f}, l[2] = {0.f, 0.f};

        // prefetch tile 0 into buffer 0 (head-major: row stride = 64 halves)
        cp16(kby[0] + prow0 * VROWB + poff0, kh + prow0 * DHH + (poff0 >> 1));
        cp16(kby[0] + prow1 * VROWB + poff1, kh + prow1 * DHH + (poff1 >> 1));
        cp16(vby[0] + prow0 * VROWB + poff0, vh + prow0 * DHH + (poff0 >> 1));
        cp16(vby[0] + prow1 * VROWB + poff1, vh + prow1 * DHH + (poff1 >> 1));
        cp_commit();

        for (int kt = 0; kt < SS / KT; kt++) {
            cp_wait0();
            __syncthreads();
            if (kt < SS / KT - 1) {
                int nb = (kt + 1) & 1;
                size_t e0 = (size_t)(kt + 1) * (KT * DHH);
                cp16(kby[nb] + prow0 * VROWB + poff0, kh + e0 + prow0 * DHH + (poff0 >> 1));
                cp16(kby[nb] + prow1 * VROWB + poff1, kh + e0 + prow1 * DHH + (poff1 >> 1));
                cp16(vby[nb] + prow0 * VROWB + poff0, vh + e0 + prow0 * DHH + (poff0 >> 1));
                cp16(vby[nb] + prow1 * VROWB + poff1, vh + e0 + prow1 * DHH + (poff1 >> 1));
            }
            cp_commit();

            const uint32_t* K = sm + ((kt & 1) ? SM_K1 : SM_K0);
            const uint32_t vba = vb32[kt & 1];

            // S = Q K^T : 16q x 64k per warp (A from regs)
            float s[8][4];
#pragma unroll
            for (int n = 0; n < 8; n++)
#pragma unroll
                for (int j = 0; j < 4; j++) s[n][j] = 0.f;
#pragma unroll
            for (int g = 0; g < 4; g++) {
#pragma unroll
                for (int n = 0; n < 8; n++) {
                    const uint32_t* kp = K + (n * 8 + r4) * LDH + g * 8 + c4;
                    mma16(s[n], qA[g][0], qA[g][1], qA[g][2], qA[g][3], kp[0], kp[4]);
                }
            }

            // Online softmax, log2 domain
#pragma unroll
            for (int hh = 0; hh < 2; hh++) {
                float rm = -1e30f;
#pragma unroll
                for (int n = 0; n < 8; n++) {
                    s[n][hh * 2]     *= SCL;
                    s[n][hh * 2 + 1] *= SCL;
                    rm = fmaxf(rm, fmaxf(s[n][hh * 2], s[n][hh * 2 + 1]));
                }
                rm = fmaxf(rm, __shfl_xor_sync(0xffffffffu, rm, 1));
                rm = fmaxf(rm, __shfl_xor_sync(0xffffffffu, rm, 2));
                float nm = fmaxf(mx[hh], rm);
                float alpha = ex2f(mx[hh] - nm);
                mx[hh] = nm;
                float rs = 0.f;
                uint32_t* prow = Ps + (wq + hh * 8 + r4) * LDH + c4;
#pragma unroll
                for (int n = 0; n < 8; n++) {
                    float p0 = ex2f(s[n][hh * 2] - nm);
                    float p1 = ex2f(s[n][hh * 2 + 1] - nm);
                    rs += p0 + p1;
                    prow[n * 4] = f2h2(p0, p1);
                }
                rs += __shfl_xor_sync(0xffffffffu, rs, 1);
                rs += __shfl_xor_sync(0xffffffffu, rs, 2);
                l[hh] = l[hh] * alpha + rs;
#pragma unroll
                for (int n = 0; n < 8; n++) {
                    o[n][hh * 2]     *= alpha;
                    o[n][hh * 2 + 1] *= alpha;
                }
            }
            __syncwarp();

            // O += P V (V fragments via ldmatrix.trans)
#pragma unroll
            for (int g = 0; g < 4; g++) {
                const uint32_t* pp = Ps + (wq + r4) * LDH + g * 8 + c4;
                uint32_t a0 = pp[0], a1 = pp[8 * LDH], a2 = pp[4], a3 = pp[8 * LDH + 4];
                const uint32_t va = vba + g * 16 * VROWB;
#pragma unroll
                for (int n = 0; n < 8; n += 2) {
                    uint32_t b0, b1, b2, b3;
                    ldsm4t(b0, b1, b2, b3, va + n * 16);
                    mma16(o[n],     a0, a1, a2, a3, b0, b1);
                    mma16(o[n + 1], a0, a1, a2, a3, b2, b3);
                }
            }
        }
        __syncthreads();   // tiles & P quiescent before next stage staging

        // Hs += O / l  (thread-private fragment elements; no sync needed)
        float inv0 = 1.f / l[0], inv1 = 1.f / l[1];
#pragma unroll
        for (int n = 0; n < 8; n++) {
            float2* p0 = (float2*)(Hs + (wq + r4) * 68 + n * 8 + c4 * 2);
            float2* p1 = (float2*)(Hs + (wq + 8 + r4) * 68 + n * 8 + c4 * 2);
            float2 v0 = *p0, v1 = *p1;
            v0.x += o[n][0] * inv0; v0.y += o[n][1] * inv0;
            v1.x += o[n][2] * inv1; v1.y += o[n][3] * inv1;
            *p0 = v0; *p1 = v1;
        }
    }

    // ---- write Hs to out (coalesced) ----
    __syncthreads();
#pragma unroll
    for (int it = 0; it < 8; it++) {
        int idx = tid + it * 256;
        int row = idx >> 4, d4 = (idx & 15) * 4;
        *(float4*)(out + base + (size_t)(q0r + row) * DD + d4) =
            *(const float4*)(Hs + row * 68 + d4);
    }
}

// ---------------------------------------------------------------------------
extern "C" void kernel_launch(void* const* d_in, const int* in_sizes, int n_in,
                              void* d_out, int out_size) {
    const float* x     = (const float*)d_in[0];
    const float* W     = (const float*)d_in[1];
    const float* scale = (const float*)d_in[2];
    const float* gamma = (const float*)d_in[3];
    const float* beta  = (const float*)d_in[4];
    const float* mask  = (const float*)d_in[5];
    const float* resid = (const float*)d_in[6];
    const float* attnb = (const float*)d_in[7];
    const float* posb  = (const float*)d_in[8];
    float* out = (float*)d_out;

    const int ATTN_SMEM = SM_WORDS * 4;   // 90112 B
    cudaFuncSetAttribute(fused_attn, cudaFuncAttributeMaxDynamicSharedMemorySize, ATTN_SMEM);

    float* h0;
    cudaGetSymbolAddress((void**)&h0, d_h0);
    __half *kh, *vh;
    cudaGetSymbolAddress((void**)&kh, d_kh);
    cudaGetSymbolAddress((void**)&vh, d_vh);

    // preconvert all K/V to fp16 head-major
    conv_kernel<<<dim3(SS / 16, BB * HH, 12), 256>>>(
        (const float*)d_in[10], (const float*)d_in[13], (const float*)d_in[16],
        (const float*)d_in[19], (const float*)d_in[22], (const float*)d_in[25],
        (const float*)d_in[11], (const float*)d_in[14], (const float*)d_in[17],
        (const float*)d_in[20], (const float*)d_in[23], (const float*)d_in[26]);

    zero_stats_kernel<<<4, 256>>>();
    gemm_kernel<<<dim3(16, 32), 256>>>(x, W, scale);
    stats_partial_kernel<<<64, 256>>>();
    finalize_kernel<<<4, 256>>>(gamma, beta);
    post_kernel<<<4096, 256>>>(mask, resid, attnb, posb);

    fused_attn<<<dim3(BB * HH, SS / QT), 256, ATTN_SMEM>>>(
        h0,
        (const float*)d_in[9],  (const float*)d_in[12], (const float*)d_in[15],
        (const float*)d_in[18], (const float*)d_in[21], (const float*)d_in[24],
        kh, vh, out);
}

// round 11
// speedup vs baseline: 1.4550x; 1.4550x over previous
#include <cuda_runtime.h>
#include <cuda_fp16.h>
#include <cstdint>

// Problem constants (fixed shapes)
#define BB 4
#define SS 1024
#define DD 1024
#define HH 16
#define DHH 64
#define RR (BB*SS)        // 4096 rows
#define NELEM (RR*DD)     // 4194304

// Scratch (device globals: no allocation allowed)
__device__ float d_g[NELEM];    // GEMM output (pre-BN)
__device__ float d_h0[NELEM];   // ping
__device__ float d_h1[NELEM];   // pong
__device__ float g_sum[DD];
__device__ float g_sqsum[DD];
__device__ float g_nmul[DD];
__device__ float g_nadd[DD];

// ---------------------------------------------------------------------------
// helpers
// ---------------------------------------------------------------------------
__device__ __forceinline__ uint32_t f2h2(float a, float b) {
    __half2 h = __floats2half2_rn(a, b);
    return *(uint32_t*)&h;
}

__device__ __forceinline__ float ex2f(float x) {
    float r; asm("ex2.approx.f32 %0, %1;" : "=f"(r) : "f"(x)); return r;
}

__device__ __forceinline__ uint32_t ex2h2(uint32_t x) {
    uint32_t r; asm("ex2.approx.f16x2 %0, %1;" : "=r"(r) : "r"(x)); return r;
}

__device__ __forceinline__ void mma16(float* c,
                                      uint32_t a0, uint32_t a1, uint32_t a2, uint32_t a3,
                                      uint32_t b0, uint32_t b1) {
    asm volatile("mma.sync.aligned.m16n8k16.row.col.f32.f16.f16.f32 "
                 "{%0,%1,%2,%3},{%4,%5,%6,%7},{%8,%9},{%0,%1,%2,%3};"
                 : "+f"(c[0]), "+f"(c[1]), "+f"(c[2]), "+f"(c[3])
                 : "r"(a0), "r"(a1), "r"(a2), "r"(a3), "r"(b0), "r"(b1));
}

__device__ __forceinline__ void ldsm4(uint32_t& r0, uint32_t& r1, uint32_t& r2, uint32_t& r3,
                                      uint32_t addr) {
    asm volatile("ldmatrix.sync.aligned.m8n8.x4.shared.b16 {%0,%1,%2,%3}, [%4];"
                 : "=r"(r0), "=r"(r1), "=r"(r2), "=r"(r3) : "r"(addr));
}

__device__ __forceinline__ void ldsm4t(uint32_t& r0, uint32_t& r1, uint32_t& r2, uint32_t& r3,
                                       uint32_t addr) {
    asm volatile("ldmatrix.sync.aligned.m8n8.x4.trans.shared.b16 {%0,%1,%2,%3}, [%4];"
                 : "=r"(r0), "=r"(r1), "=r"(r2), "=r"(r3) : "r"(addr));
}

__device__ __forceinline__ uint32_t smem_u32(const void* p) {
    uint32_t a;
    asm("{ .reg .u64 t; cvta.to.shared.u64 t, %1; cvt.u32.u64 %0, t; }" : "=r"(a) : "l"(p));
    return a;
}

// ---------------------------------------------------------------------------
// GEMM: d_g[r,o] = (sum_i x[r,i] * W[o,i]) * scale[o]   (fp16 MMA, fp32 acc)
// ---------------------------------------------------------------------------
#define LDW 36

__global__ __launch_bounds__(256) void gemm_kernel(const float* __restrict__ x,
                                                   const float* __restrict__ W,
                                                   const float* __restrict__ scale) {
    __shared__ __align__(16) uint32_t Xs[128 * LDW];
    __shared__ __align__(16) uint32_t Ws[64 * LDW];
    const int tid = threadIdx.x;
    const int lane = tid & 31, w = tid >> 5;
    const int wq = w * 16;
    const int r4 = lane >> 2, c4 = lane & 3;
    const int r0 = blockIdx.y * 128, o0 = blockIdx.x * 64;

    float acc[8][4];
#pragma unroll
    for (int n = 0; n < 8; n++)
#pragma unroll
        for (int j = 0; j < 4; j++) acc[n][j] = 0.f;

    for (int k0 = 0; k0 < DD; k0 += 64) {
#pragma unroll
        for (int it = 0; it < 8; it++) {
            int idx = tid + it * 256;
            int r = idx >> 4, d4 = (idx & 15) * 4;
            float4 v = *(const float4*)(x + (size_t)(r0 + r) * DD + k0 + d4);
            uint32_t* dst = Xs + r * LDW + (idx & 15) * 2;
            dst[0] = f2h2(v.x, v.y); dst[1] = f2h2(v.z, v.w);
        }
#pragma unroll
        for (int it = 0; it < 4; it++) {
            int idx = tid + it * 256;
            int r = idx >> 4, d4 = (idx & 15) * 4;
            float4 v = *(const float4*)(W + (size_t)(o0 + r) * DD + k0 + d4);
            uint32_t* dst = Ws + r * LDW + (idx & 15) * 2;
            dst[0] = f2h2(v.x, v.y); dst[1] = f2h2(v.z, v.w);
        }
        __syncthreads();

#pragma unroll
        for (int k16 = 0; k16 < 4; k16++) {
            const uint32_t* xp = Xs + (wq + r4) * LDW + k16 * 8 + c4;
            uint32_t a0 = xp[0], a1 = xp[8 * LDW], a2 = xp[4], a3 = xp[8 * LDW + 4];
#pragma unroll
            for (int n = 0; n < 8; n++) {
                const uint32_t* wp = Ws + (n * 8 + r4) * LDW + k16 * 8 + c4;
                mma16(acc[n], a0, a1, a2, a3, wp[0], wp[4]);
            }
        }
        __syncthreads();
    }

#pragma unroll
    for (int h = 0; h < 2; h++) {
        int row = r0 + wq + h * 8 + r4;
#pragma unroll
        for (int n = 0; n < 8; n++) {
            float2 sc = *(const float2*)(scale + o0 + n * 8 + c4 * 2);
            float2 ov = make_float2(acc[n][h * 2] * sc.x, acc[n][h * 2 + 1] * sc.y);
            *(float2*)(d_g + (size_t)row * DD + o0 + n * 8 + c4 * 2) = ov;
        }
    }
}

// ---------------------------------------------------------------------------
// BatchNorm statistics
// ---------------------------------------------------------------------------
__global__ __launch_bounds__(256) void zero_stats_kernel() {
    int i = blockIdx.x * 256 + threadIdx.x;
    if (i < DD) { g_sum[i] = 0.f; g_sqsum[i] = 0.f; }
}

__global__ __launch_bounds__(256) void stats_partial_kernel() {
    int r0 = blockIdx.x * 16;
    float s[4] = {0.f, 0.f, 0.f, 0.f};
    float ss[4] = {0.f, 0.f, 0.f, 0.f};
    for (int r = 0; r < 16; r++) {
        const float* row = d_g + (size_t)(r0 + r) * DD;
#pragma unroll
        for (int c = 0; c < 4; c++) {
            float v = row[threadIdx.x + c * 256];
            s[c] += v; ss[c] += v * v;
        }
    }
#pragma unroll
    for (int c = 0; c < 4; c++) {
        atomicAdd(&g_sum[threadIdx.x + c * 256], s[c]);
        atomicAdd(&g_sqsum[threadIdx.x + c * 256], ss[c]);
    }
}

__global__ __launch_bounds__(256) void finalize_kernel(const float* __restrict__ gamma,
                                                       const float* __restrict__ beta) {
    int f = blockIdx.x * 256 + threadIdx.x;
    if (f < DD) {
        float mu = g_sum[f] * (1.f / RR);
        float var = g_sqsum[f] * (1.f / RR) - mu * mu;
        float rs = rsqrtf(var + 1e-5f);
        float gm = gamma[f] * rs;
        g_nmul[f] = gm;
        g_nadd[f] = beta[f] - gm * mu;
    }
}

// ---------------------------------------------------------------------------
// Elementwise epilogue -> d_h0
// ---------------------------------------------------------------------------
__global__ __launch_bounds__(256) void post_kernel(const float* __restrict__ mask,
                                                   const float* __restrict__ resid,
                                                   const float* __restrict__ attn,
                                                   const float* __restrict__ pos) {
    int i = blockIdx.x * 256 + threadIdx.x;
    int fb = (i & 255) * 4;
    float4 gv = *(const float4*)(d_g + (size_t)i * 4);
    float4 mk = ((const float4*)mask)[i];
    float4 rv = ((const float4*)resid)[i];
    float4 av = ((const float4*)attn)[i];
    float4 pv = ((const float4*)pos)[i];
    float g[4] = {gv.x, gv.y, gv.z, gv.w};
    float m[4] = {mk.x, mk.y, mk.z, mk.w};
    float r[4] = {rv.x, rv.y, rv.z, rv.w};
    float a[4] = {av.x, av.y, av.z, av.w};
    float p[4] = {pv.x, pv.y, pv.z, pv.w};
    float o[4];
#pragma unroll
    for (int c = 0; c < 4; c++) {
        float h = g[c] * g_nmul[fb + c] + g_nadd[fb + c];
        h = fmaxf(h, 0.f) * m[c];
        o[c] = h + r[c] + a[c] + p[c];
    }
    *(float4*)(d_h0 + (size_t)i * 4) = make_float4(o[0], o[1], o[2], o[3]);
}

// ---------------------------------------------------------------------------
// Flash attention stage (unfused, one stage per launch):
//   h_out = h_in + MHA(h_in + qb, kb, vb)
// Block: (b,h) x q-tile 128; 8 warps, warp w owns q-rows [w*16, w*16+16).
// - Q pre-scaled by SCL, held in registers (staged once through Ks).
// - K/V loaded fp32->fp16 per 128-key tile (static smem, 2 syncs per tile).
// - K B-fragments via ldmatrix.x4; V via ldmatrix.x4.trans.
// - P stays in registers (C-frag == A-frag layout).
// - Row sum l computed by a ones-column MMA (fp32, same rescale as O).
// ---------------------------------------------------------------------------
#define QT 128
#define KT 128
#define LDH 36                       // uint32 (half2) row stride
#define ROWB (LDH * 4)               // 144 bytes
#define SCL 0.18033688f              // (1/sqrt(64)) * log2(e)

__global__ __launch_bounds__(256, 2) void attn_kernel(const float* __restrict__ h_in,
                                                      const float* __restrict__ qb,
                                                      const float* __restrict__ kb,
                                                      const float* __restrict__ vb,
                                                      float* __restrict__ h_out) {
    __shared__ __align__(16) uint32_t Ks[KT * LDH];   // keys x d (half2)
    __shared__ __align__(16) uint32_t Vs[KT * LDH];

    const int tid = threadIdx.x;
    const int lane = tid & 31, w = tid >> 5;
    const int wq = w * 16;
    const int r4 = lane >> 2, c4 = lane & 3;

    const int bh = blockIdx.x;
    const int b = bh >> 4, hd = bh & 15;
    const int q0r = blockIdx.y * QT;
    const size_t base = (size_t)b * (SS * DD) + (size_t)hd * DHH;

    // ldmatrix address bases
    const uint32_t ksb = smem_u32(Ks);
    const uint32_t vsb = smem_u32(Vs);
    // K (non-trans): lanes 0-7 m0 rows, 8-15 m1 (+16B), 16-23 m2 (+8 rows), 24-31 m3
    const uint32_t kaddr = ksb + ((lane & 7) + ((lane & 16) >> 1)) * ROWB + ((lane & 8) << 1);
    // V (trans): lanes 0-15 -> key rows, lanes 16-31 -> +16B
    const uint32_t vaddr = vsb + (lane & 15) * ROWB + ((lane >> 4) << 4);
    // ones-column B fragment (col 0 of a virtual n-tile = 1, rest 0)
    const uint32_t onesB = (r4 == 0) ? 0x3C003C00u : 0u;

    // ---- stage Q = (h_in + qb) * SCL through Ks, build A-fragments ----
#pragma unroll
    for (int it = 0; it < 8; it++) {
        int idx = tid + it * 256;
        int row = idx >> 4, d4 = (idx & 15) * 4;
        size_t g = base + (size_t)(q0r + row) * DD + d4;
        float4 a = *(const float4*)(h_in + g);
        float4 q = *(const float4*)(qb + g);
        uint32_t* dst = Ks + row * LDH + (idx & 15) * 2;
        dst[0] = f2h2((a.x + q.x) * SCL, (a.y + q.y) * SCL);
        dst[1] = f2h2((a.z + q.z) * SCL, (a.w + q.w) * SCL);
    }
    __syncthreads();
    uint32_t qA[4][4];
#pragma unroll
    for (int g = 0; g < 4; g++) {
        const uint32_t* qp = Ks + (wq + r4) * LDH + g * 8 + c4;
        qA[g][0] = qp[0]; qA[g][1] = qp[8 * LDH];
        qA[g][2] = qp[4]; qA[g][3] = qp[8 * LDH + 4];
    }
    __syncthreads();   // all qA reads done before K tile 0 overwrites Ks

    float o[8][4];
    float osum[4] = {0.f, 0.f, 0.f, 0.f};
    float mx[2] = {-1e30f, -1e30f};
#pragma unroll
    for (int n = 0; n < 8; n++)
#pragma unroll
        for (int j = 0; j < 4; j++) o[n][j] = 0.f;

    for (int kt = 0; kt < SS / KT; kt++) {
        const int k0 = kt * KT;
        // ---- load K/V tile (fp32 -> half2) ----
#pragma unroll
        for (int it = 0; it < 8; it++) {
            int idx = tid + it * 256;
            int row = idx >> 4, d4 = (idx & 15) * 4;
            size_t g = base + (size_t)(k0 + row) * DD + d4;
            float4 kv = *(const float4*)(kb + g);
            float4 vv = *(const float4*)(vb + g);
            uint32_t* dk = Ks + row * LDH + (idx & 15) * 2;
            dk[0] = f2h2(kv.x, kv.y); dk[1] = f2h2(kv.z, kv.w);
            uint32_t* dv = Vs + row * LDH + (idx & 15) * 2;
            dv[0] = f2h2(vv.x, vv.y); dv[1] = f2h2(vv.z, vv.w);
        }
        __syncthreads();

#pragma unroll
        for (int sub = 0; sub < 2; sub++) {
            // ---- S = Q K^T over 64 keys (n-tiles 0..7 of this sub) ----
            float s[8][4];
#pragma unroll
            for (int n = 0; n < 8; n++)
#pragma unroll
                for (int j = 0; j < 4; j++) s[n][j] = 0.f;
#pragma unroll
            for (int g = 0; g < 4; g++) {
#pragma unroll
                for (int np = 0; np < 4; np++) {
                    uint32_t b0, b1, b2, b3;
                    ldsm4(b0, b1, b2, b3,
                          kaddr + (uint32_t)(sub * 64 + np * 16) * ROWB + g * 32);
                    mma16(s[2 * np],     qA[g][0], qA[g][1], qA[g][2], qA[g][3], b0, b1);
                    mma16(s[2 * np + 1], qA[g][0], qA[g][1], qA[g][2], qA[g][3], b2, b3);
                }
            }

            // ---- online softmax; P in registers (half2) ----
            uint32_t pa[8], pb[8];
#pragma unroll
            for (int hh = 0; hh < 2; hh++) {
                float rm = -1e30f;
#pragma unroll
                for (int n = 0; n < 8; n++)
                    rm = fmaxf(rm, fmaxf(s[n][hh * 2], s[n][hh * 2 + 1]));
                rm = fmaxf(rm, __shfl_xor_sync(0xffffffffu, rm, 1));
                rm = fmaxf(rm, __shfl_xor_sync(0xffffffffu, rm, 2));
                float nm = fmaxf(mx[hh], rm);
                float alpha = ex2f(mx[hh] - nm);
                mx[hh] = nm;
#pragma unroll
                for (int n = 0; n < 8; n++) {
                    uint32_t ph = ex2h2(f2h2(s[n][hh * 2] - nm, s[n][hh * 2 + 1] - nm));
                    if (hh == 0) pa[n] = ph; else pb[n] = ph;
                    o[n][hh * 2]     *= alpha;
                    o[n][hh * 2 + 1] *= alpha;
                }
                osum[hh * 2]     *= alpha;
                osum[hh * 2 + 1] *= alpha;
            }

            // ---- O += P V ; l += P * ones ----
#pragma unroll
            for (int ck = 0; ck < 4; ck++) {
                uint32_t a0 = pa[2 * ck], a1 = pb[2 * ck];
                uint32_t a2 = pa[2 * ck + 1], a3 = pb[2 * ck + 1];
                const uint32_t va = vaddr + (uint32_t)(sub * 4 + ck) * 16 * ROWB;
#pragma unroll
                for (int nd = 0; nd < 8; nd += 2) {
                    uint32_t b0, b1, b2, b3;
                    ldsm4t(b0, b1, b2, b3, va + nd * 16);
                    mma16(o[nd],     a0, a1, a2, a3, b0, b1);
                    mma16(o[nd + 1], a0, a1, a2, a3, b2, b3);
                }
                mma16(osum, a0, a1, a2, a3, onesB, onesB);
            }
        }
        __syncthreads();
    }

    // ---- finalize: l from ones-column (col 0 lives in c4==0 lanes) ----
    float l0 = __shfl_sync(0xffffffffu, osum[0], lane & 28);
    float l1 = __shfl_sync(0xffffffffu, osum[2], lane & 28);
    float inv0 = 1.f / l0, inv1 = 1.f / l1;
#pragma unroll
    for (int hh = 0; hh < 2; hh++) {
        float inv = hh ? inv1 : inv0;
        int row = q0r + wq + hh * 8 + r4;
#pragma unroll
        for (int n = 0; n < 8; n++) {
            size_t g = base + (size_t)row * DD + n * 8 + c4 * 2;
            float2 hv = *(const float2*)(h_in + g);
            float2 ov = make_float2(hv.x + o[n][hh * 2] * inv,
                                    hv.y + o[n][hh * 2 + 1] * inv);
            *(float2*)(h_out + g) = ov;
        }
    }
}

// ---------------------------------------------------------------------------
extern "C" void kernel_launch(void* const* d_in, const int* in_sizes, int n_in,
                              void* d_out, int out_size) {
    const float* x     = (const float*)d_in[0];
    const float* W     = (const float*)d_in[1];
    const float* scale = (const float*)d_in[2];
    const float* gamma = (const float*)d_in[3];
    const float* beta  = (const float*)d_in[4];
    const float* mask  = (const float*)d_in[5];
    const float* resid = (const float*)d_in[6];
    const float* attnb = (const float*)d_in[7];
    const float* posb  = (const float*)d_in[8];
    float* out = (float*)d_out;

    float *h0, *h1;
    cudaGetSymbolAddress((void**)&h0, d_h0);
    cudaGetSymbolAddress((void**)&h1, d_h1);

    zero_stats_kernel<<<4, 256>>>();
    gemm_kernel<<<dim3(16, 32), 256>>>(x, W, scale);
    stats_partial_kernel<<<256, 256>>>();
    finalize_kernel<<<4, 256>>>(gamma, beta);
    post_kernel<<<4096, 256>>>(mask, resid, attnb, posb);

    dim3 ag(BB * HH, SS / QT);   // (64, 8)
    const float* cur = h0;
    float* pong[2] = {h1, h0};
    for (int st = 0; st < 6; st++) {
        const float* q = (const float*)d_in[9 + 3 * st];
        const float* k = (const float*)d_in[10 + 3 * st];
        const float* v = (const float*)d_in[11 + 3 * st];
        float* dst = (st == 5) ? out : pong[st & 1];
        attn_kernel<<<ag, 256>>>(cur, q, k, v, dst);
        cur = dst;
    }
}